// round 14
// baseline (speedup 1.0000x reference)
#include <cuda_runtime.h>
#include <cfloat>

// Problem constants (from reference)
#define PB 7      // pooled bins per dim
#define HH 50
#define WW 50
#define CC 512
#define BB 2
#define RR 64
#define C4 (CC / 4)     // 128 float4 per pixel
#define NROI (BB * RR)  // 128
#define GPO  48         // CTAs per (py,px) group
#define NCTA (PB * PB * GPO)   // 2352 = 49*48 ~ 15.9 CTAs/SM: full residency
                               // AND fixed (py,px) per CTA (no decode in loop)

// Combines the two independently-proven properties:
//  * near-full single-wave residency (grid ~ 148*16), from R13
//  * fixed (py,px) per CTA -> zero div/mod on the per-bin path, from R12
// CTA bid: group = bid/48 -> (py,px) decoded ONCE; j = bid%48 -> handles
// rois {j, j+48, j+96} (3 rois for j<32, else 2). Next roi prefetched before
// the current gather. Integer bin bounds; CTA-uniform 16-case exact-load
// dispatch.
//
// Integer bin bounds ys = py*h/7 == reference fp32 trunc(py*(h/7.0f)) for
// h in [7,25]: exact when 7|h, else py*h/7 is >=1/7 from any integer, far
// beyond fp32 rounding error. (Validated rel_err=0.0 in R10-R13.)
//
// Facts proved from input ranges: extent in [7,26) => sy,sx in [1,4];
// window always fully in-bounds (max index y0+h-1 <= 48 < 50).

__device__ __forceinline__ void vmax(float4& m, float4 v) {
    m.x = fmaxf(m.x, v.x);
    m.y = fmaxf(m.y, v.y);
    m.z = fmaxf(m.z, v.z);
    m.w = fmaxf(m.w, v.w);
}

template<int SY, int SX>
__device__ __forceinline__ float4 binmax(const float4* __restrict__ p) {
    float4 v[SY * SX];
    #pragma unroll
    for (int dy = 0; dy < SY; ++dy)
        #pragma unroll
        for (int dx = 0; dx < SX; ++dx)
            v[dy * SX + dx] = __ldg(p + (dy * WW + dx) * C4);

    float4 m = v[0];
    #pragma unroll
    for (int k = 1; k < SY * SX; ++k)
        vmax(m, v[k]);
    return m;
}

__global__ __launch_bounds__(C4) void roipool_kernel(
    const float4* __restrict__ fm,    // (B,H,W,C) as float4
    const int*    __restrict__ rois,  // (B,R,4) int32: y0,x0,h,w
    float4*       __restrict__ out)   // (B,R,P,P,C) as float4
{
    int bid  = blockIdx.x;            // 0..2351
    int obin = bid / GPO;             // 0..48 : py*7+px, fixed for this CTA
    int j    = bid - obin * GPO;      // 0..47 : roi-group lane
    int py   = obin / PB;
    int px   = obin - py * PB;

    int c4 = threadIdx.x;             // 0..127
    bool lasty = (py == PB - 1);
    bool lastx = (px == PB - 1);

    // Prefetch first roi.
    int4 roi = __ldg((const int4*)(rois + j * 4));

    #pragma unroll
    for (int k = 0; k < 3; ++k) {
        int rid = j + GPO * k;
        if (rid >= NROI) break;       // j >= 32 does only 2 rois

        // Prefetch next roi before this bin's gather.
        int nrid = rid + GPO;
        int4 roi_n;
        if (nrid < NROI)
            roi_n = __ldg((const int4*)(rois + nrid * 4));

        int y0 = roi.x, x0 = roi.y, h = roi.z, w = roi.w;

        // Integer bin bounds (== reference fp32 result, see header).
        int ys = (py * h) / PB;
        int ye = lasty ? h : ((py + 1) * h) / PB;
        int sy = max(ye - ys, 1);
        int xs = (px * w) / PB;
        int xe = lastx ? w : ((px + 1) * w) / PB;
        int sx = max(xe - xs, 1);

        // b = rid >> 6; fm image stride = HH*WW pixels.
        const float4* p = fm
            + ((size_t)(((rid >> 6) * HH + (y0 + ys)) * WW + (x0 + xs))) * C4
            + c4;

        float4 m;
        int code = (sy - 1) * 4 + (sx - 1);   // uniform across CTA
        switch (code) {
            case  0: m = binmax<1,1>(p); break;
            case  1: m = binmax<1,2>(p); break;
            case  2: m = binmax<1,3>(p); break;
            case  3: m = binmax<1,4>(p); break;
            case  4: m = binmax<2,1>(p); break;
            case  5: m = binmax<2,2>(p); break;
            case  6: m = binmax<2,3>(p); break;
            case  7: m = binmax<2,4>(p); break;
            case  8: m = binmax<3,1>(p); break;
            case  9: m = binmax<3,2>(p); break;
            case 10: m = binmax<3,3>(p); break;
            case 11: m = binmax<3,4>(p); break;
            case 12: m = binmax<4,1>(p); break;
            case 13: m = binmax<4,2>(p); break;
            case 14: m = binmax<4,3>(p); break;
            default: m = binmax<4,4>(p); break;
        }

        // out bin index = rid*49 + obin
        out[(size_t)(rid * (PB * PB) + obin) * C4 + c4] = m;

        roi = roi_n;
    }
}

extern "C" void kernel_launch(void* const* d_in, const int* in_sizes, int n_in,
                              void* d_out, int out_size) {
    const float4* fm   = (const float4*)d_in[0];  // x_maps float32 (2,50,50,512)
    const int*    rois = (const int*)d_in[1];     // x_rois int32 (2,64,4)
    float4*       out  = (float4*)d_out;          // (2,64,7,7,512) float32

    roipool_kernel<<<NCTA, C4>>>(fm, rois, out);
}